// round 1
// baseline (speedup 1.0000x reference)
#include <cuda_runtime.h>
#include <math.h>

#define BB 32
#define SS 256
#define HH 512
#define EE 512
#define VV 32000
#define LL 64
#define SOS_TOK 1
#define XD 1024          // H + ENC
#define G3 1536          // 3*H

// ---------------- scratch (device globals; no allocations allowed) -------
__device__ float g_h[BB * HH];            // hidden state (B,H)
__device__ float g_Uk[BB * SS * HH];      // Ua(keys) (B*S, H)  ~16.8MB
__device__ float g_x[BB * XD];            // [emb | ctx]  (B, 1024)
__device__ float g_gi_part[4 * BB * G3];  // split-K partials for gi
__device__ float g_gh_part[2 * BB * G3];  // split-K partials for gh
__device__ float g_logits[BB * VV];       // (B, V) ~4.1MB

// ---------------- generic tiled GEMM: C = A @ Bw^T (+bias) ---------------
// A: (M, ld) row-major, rows m0+0..31 used per block (M multiple of 32 via grid.y)
// Bw: (N, ld) row-major. C[m*N+n]. kLen per z-slice; kStart = z*kLen.
// When gridDim.z>1, each z writes its partial to C + z*partStride (no bias).
// Requires: N % 64 == 0, kLen % 32 == 0, 16B alignment of rows (ld%4==0).
__global__ void __launch_bounds__(128)
gemm32(const float* __restrict__ A, const float* __restrict__ Bw,
       const float* __restrict__ bias, float* __restrict__ C,
       int N, int ld, int kLen, int partStride) {
    __shared__ float As[32][33];
    __shared__ float Bs[32][65];
    const int tid = threadIdx.x;          // 128 threads
    const int n0 = blockIdx.x * 64;
    const int m0 = blockIdx.y * 32;
    const int kStart = blockIdx.z * kLen;
    float* Cz = C + (size_t)blockIdx.z * (size_t)partStride;

    const int la_m = tid >> 2;            // 0..31
    const int la_k = (tid & 3) << 2;      // 0,4,8,12
    const int lb_n = tid >> 1;            // 0..63
    const int lb_k = (tid & 1) << 2;      // 0,4

    const int tm = tid >> 4;              // 0..7  -> m = tm*4+i
    const int tn = tid & 15;              // 0..15 -> n = tn*4+j

    float acc[4][4];
#pragma unroll
    for (int i = 0; i < 4; i++)
#pragma unroll
        for (int j = 0; j < 4; j++) acc[i][j] = 0.f;

    const float* Arow = A + (size_t)(m0 + la_m) * ld + kStart;
    const float* Brow = Bw + (size_t)(n0 + lb_n) * ld + kStart;

    for (int k0 = 0; k0 < kLen; k0 += 32) {
        float4 av0 = *reinterpret_cast<const float4*>(Arow + k0 + la_k);
        float4 av1 = *reinterpret_cast<const float4*>(Arow + k0 + la_k + 16);
        As[la_k + 0][la_m] = av0.x;  As[la_k + 1][la_m] = av0.y;
        As[la_k + 2][la_m] = av0.z;  As[la_k + 3][la_m] = av0.w;
        As[la_k + 16][la_m] = av1.x; As[la_k + 17][la_m] = av1.y;
        As[la_k + 18][la_m] = av1.z; As[la_k + 19][la_m] = av1.w;

        float4 bv0 = *reinterpret_cast<const float4*>(Brow + k0 + lb_k);
        float4 bv1 = *reinterpret_cast<const float4*>(Brow + k0 + lb_k + 8);
        float4 bv2 = *reinterpret_cast<const float4*>(Brow + k0 + lb_k + 16);
        float4 bv3 = *reinterpret_cast<const float4*>(Brow + k0 + lb_k + 24);
        Bs[lb_k + 0][lb_n] = bv0.x;  Bs[lb_k + 1][lb_n] = bv0.y;
        Bs[lb_k + 2][lb_n] = bv0.z;  Bs[lb_k + 3][lb_n] = bv0.w;
        Bs[lb_k + 8][lb_n] = bv1.x;  Bs[lb_k + 9][lb_n] = bv1.y;
        Bs[lb_k + 10][lb_n] = bv1.z; Bs[lb_k + 11][lb_n] = bv1.w;
        Bs[lb_k + 16][lb_n] = bv2.x; Bs[lb_k + 17][lb_n] = bv2.y;
        Bs[lb_k + 18][lb_n] = bv2.z; Bs[lb_k + 19][lb_n] = bv2.w;
        Bs[lb_k + 24][lb_n] = bv3.x; Bs[lb_k + 25][lb_n] = bv3.y;
        Bs[lb_k + 26][lb_n] = bv3.z; Bs[lb_k + 27][lb_n] = bv3.w;
        __syncthreads();

#pragma unroll
        for (int kk = 0; kk < 32; kk++) {
            float a0 = As[kk][tm * 4 + 0];
            float a1 = As[kk][tm * 4 + 1];
            float a2 = As[kk][tm * 4 + 2];
            float a3 = As[kk][tm * 4 + 3];
            float b0 = Bs[kk][tn * 4 + 0];
            float b1 = Bs[kk][tn * 4 + 1];
            float b2 = Bs[kk][tn * 4 + 2];
            float b3 = Bs[kk][tn * 4 + 3];
            acc[0][0] += a0 * b0; acc[0][1] += a0 * b1; acc[0][2] += a0 * b2; acc[0][3] += a0 * b3;
            acc[1][0] += a1 * b0; acc[1][1] += a1 * b1; acc[1][2] += a1 * b2; acc[1][3] += a1 * b3;
            acc[2][0] += a2 * b0; acc[2][1] += a2 * b1; acc[2][2] += a2 * b2; acc[2][3] += a2 * b3;
            acc[3][0] += a3 * b0; acc[3][1] += a3 * b1; acc[3][2] += a3 * b2; acc[3][3] += a3 * b3;
        }
        __syncthreads();
    }

#pragma unroll
    for (int i = 0; i < 4; i++) {
        int m = m0 + tm * 4 + i;
        float* crow = Cz + (size_t)m * N + n0 + tn * 4;
#pragma unroll
        for (int j = 0; j < 4; j++) {
            float v = acc[i][j];
            if (bias) v += bias[n0 + tn * 4 + j];
            crow[j] = v;
        }
    }
}

// ---------------- fused attention step (one block per batch row) ---------
// Computes q = h@Wa^T+ba, scores = Va.tanh(q+Uk)+bVa, softmax -> w,
// writes attentions[b,t,:], ctx = w @ enc[b], assembles x = [emb(tok) | ctx].
__global__ void __launch_bounds__(512)
att_step(const float* __restrict__ enc, const int* __restrict__ tgt,
         const float* __restrict__ emb,
         const float* __restrict__ Wa, const float* __restrict__ ba,
         const float* __restrict__ Va, const float* __restrict__ bVa,
         float* __restrict__ out_attn, int t) {
    const int b = blockIdx.x;
    const int tid = threadIdx.x;       // 512
    const int lane = tid & 31;
    const int wrp = tid >> 5;          // 16 warps
    __shared__ float sh_h[HH];
    __shared__ float sh_q[HH];
    __shared__ float sh_s[SS];
    __shared__ float red[32];

    sh_h[tid] = g_h[b * HH + tid];
    __syncthreads();

    // ---- q[i] = h . Wa[i,:] + ba[i] (warp per i, coalesced float4) ----
    const float4* h4 = reinterpret_cast<const float4*>(sh_h);
    for (int i = wrp; i < HH; i += 16) {
        const float4* w4 = reinterpret_cast<const float4*>(Wa + (size_t)i * HH);
        float p = 0.f;
#pragma unroll
        for (int c = 0; c < 4; c++) {
            float4 wv = w4[lane + 32 * c];
            float4 hv = h4[lane + 32 * c];
            p += wv.x * hv.x + wv.y * hv.y + wv.z * hv.z + wv.w * hv.w;
        }
        for (int o = 16; o; o >>= 1) p += __shfl_xor_sync(0xffffffffu, p, o);
        if (lane == 0) sh_q[i] = p + ba[i];
    }
    __syncthreads();

    // ---- scores[s] = sum_j Va[j]*tanh(q[j]+Uk[b,s,j]) + bVa ----
    const float4* q4 = reinterpret_cast<const float4*>(sh_q);
    const float4* va4 = reinterpret_cast<const float4*>(Va);
    for (int s = wrp; s < SS; s += 16) {
        const float4* u4 = reinterpret_cast<const float4*>(g_Uk + ((size_t)(b * SS + s)) * HH);
        float p = 0.f;
#pragma unroll
        for (int c = 0; c < 4; c++) {
            float4 uv = u4[lane + 32 * c];
            float4 qv = q4[lane + 32 * c];
            float4 vv = va4[lane + 32 * c];
            p += vv.x * tanhf(qv.x + uv.x) + vv.y * tanhf(qv.y + uv.y)
               + vv.z * tanhf(qv.z + uv.z) + vv.w * tanhf(qv.w + uv.w);
        }
        for (int o = 16; o; o >>= 1) p += __shfl_xor_sync(0xffffffffu, p, o);
        if (lane == 0) sh_s[s] = p + bVa[0];
    }
    __syncthreads();

    // ---- softmax over S=256 ----
    float v = (tid < SS) ? sh_s[tid] : -1e30f;
    float mx = v;
    for (int o = 16; o; o >>= 1) mx = fmaxf(mx, __shfl_xor_sync(0xffffffffu, mx, o));
    if (lane == 0) red[wrp] = mx;
    __syncthreads();
    if (tid == 0) {
        float mm = -1e30f;
        for (int i = 0; i < 16; i++) mm = fmaxf(mm, red[i]);
        red[0] = mm;
    }
    __syncthreads();
    float gmax = red[0];
    __syncthreads();
    float e = (tid < SS) ? expf(v - gmax) : 0.f;
    float ssum = e;
    for (int o = 16; o; o >>= 1) ssum += __shfl_xor_sync(0xffffffffu, ssum, o);
    if (lane == 0) red[wrp] = ssum;
    __syncthreads();
    if (tid == 0) {
        float s = 0.f;
        for (int i = 0; i < 16; i++) s += red[i];
        red[0] = s;
    }
    __syncthreads();
    float inv = 1.f / red[0];
    if (tid < SS) {
        float wgt = e * inv;
        sh_s[tid] = wgt;
        out_attn[((size_t)b * LL + t) * SS + tid] = wgt;
    }
    __syncthreads();

    // ---- ctx[e] = sum_s w[s]*enc[b,s,e]; assemble x = [emb(tok) | ctx] --
    {
        float a0 = 0.f, a1 = 0.f, a2 = 0.f, a3 = 0.f;
        const float* ep = enc + ((size_t)b * SS) * EE + tid;
        for (int s = 0; s < SS; s += 4) {
            a0 += sh_s[s + 0] * ep[(size_t)(s + 0) * EE];
            a1 += sh_s[s + 1] * ep[(size_t)(s + 1) * EE];
            a2 += sh_s[s + 2] * ep[(size_t)(s + 2) * EE];
            a3 += sh_s[s + 3] * ep[(size_t)(s + 3) * EE];
        }
        g_x[b * XD + HH + tid] = (a0 + a1) + (a2 + a3);
    }
    int tok = (t == 0) ? SOS_TOK : tgt[b * LL + (t - 1)];
    g_x[b * XD + tid] = emb[(size_t)tok * HH + tid];
}

// ---------------- GRU gate combine (sums split-K partials) ---------------
__global__ void gru_gate(const float* __restrict__ b_ih, const float* __restrict__ b_hh) {
    int idx = blockIdx.x * blockDim.x + threadIdx.x;   // < B*H
    int b = idx >> 9, i = idx & 511;
    int base = b * G3;
    float gir = b_ih[i], giz = b_ih[HH + i], gin = b_ih[2 * HH + i];
#pragma unroll
    for (int p = 0; p < 4; p++) {
        const float* gp = g_gi_part + (size_t)p * BB * G3 + base;
        gir += gp[i]; giz += gp[HH + i]; gin += gp[2 * HH + i];
    }
    float ghr = b_hh[i], ghz = b_hh[HH + i], ghn = b_hh[2 * HH + i];
#pragma unroll
    for (int p = 0; p < 2; p++) {
        const float* gp = g_gh_part + (size_t)p * BB * G3 + base;
        ghr += gp[i]; ghz += gp[HH + i]; ghn += gp[2 * HH + i];
    }
    float r = 1.f / (1.f + expf(-(gir + ghr)));
    float z = 1.f / (1.f + expf(-(giz + ghz)));
    float n = tanhf(gin + r * ghn);
    float h = g_h[idx];
    g_h[idx] = (1.f - z) * n + z * h;
}

// ---------------- log_softmax over V, written to output -------------------
__global__ void __launch_bounds__(1024)
lsm_kernel(float* __restrict__ out, int t) {
    const int b = blockIdx.x;
    const int tid = threadIdx.x;
    const int lane = tid & 31, wrp = tid >> 5;
    __shared__ float red[32];
    const float* row = g_logits + (size_t)b * VV;

    float m = -1e30f;
    for (int v = tid; v < VV; v += 1024) m = fmaxf(m, row[v]);
    for (int o = 16; o; o >>= 1) m = fmaxf(m, __shfl_xor_sync(0xffffffffu, m, o));
    if (lane == 0) red[wrp] = m;
    __syncthreads();
    if (wrp == 0) {
        float x = red[lane];
        for (int o = 16; o; o >>= 1) x = fmaxf(x, __shfl_xor_sync(0xffffffffu, x, o));
        if (lane == 0) red[0] = x;
    }
    __syncthreads();
    float gm = red[0];
    __syncthreads();
    float s = 0.f;
    for (int v = tid; v < VV; v += 1024) s += expf(row[v] - gm);
    for (int o = 16; o; o >>= 1) s += __shfl_xor_sync(0xffffffffu, s, o);
    if (lane == 0) red[wrp] = s;
    __syncthreads();
    if (wrp == 0) {
        float x = red[lane];
        for (int o = 16; o; o >>= 1) x += __shfl_xor_sync(0xffffffffu, x, o);
        if (lane == 0) red[0] = x;
    }
    __syncthreads();
    float lse = gm + logf(red[0]);
    float* o = out + ((size_t)b * LL + t) * VV;
    for (int v = tid; v < VV; v += 1024) o[v] = row[v] - lse;
}

__global__ void copy_h(float* __restrict__ out_h) {
    int i = blockIdx.x * blockDim.x + threadIdx.x;
    out_h[i] = g_h[i];
}

// --------------------------------------------------------------------------
extern "C" void kernel_launch(void* const* d_in, const int* in_sizes, int n_in,
                              void* d_out, int out_size) {
    const float* enc   = (const float*)d_in[0];   // (B,S,ENC)
    const float* ehid  = (const float*)d_in[1];   // (1,B,ENC)
    const int*   tgt   = (const int*)d_in[2];     // (B,L) int32 (jax x64 off)
    const float* W_ht  = (const float*)d_in[3];   // (H,ENC)
    const float* b_ht  = (const float*)d_in[4];
    const float* emb   = (const float*)d_in[5];   // (V,H)
    const float* Wa    = (const float*)d_in[6];   // (H,H)
    const float* ba    = (const float*)d_in[7];
    const float* Ua    = (const float*)d_in[8];   // (H,ENC)
    const float* bUa   = (const float*)d_in[9];
    const float* Va    = (const float*)d_in[10];  // (1,H)
    const float* bVa   = (const float*)d_in[11];
    const float* W_ih  = (const float*)d_in[12];  // (3H, ENC+H)
    const float* W_hh  = (const float*)d_in[13];  // (3H, H)
    const float* b_ih  = (const float*)d_in[14];
    const float* b_hh  = (const float*)d_in[15];
    const float* W_out = (const float*)d_in[16];  // (V,H)
    const float* b_out = (const float*)d_in[17];

    float* out    = (float*)d_out;
    float* out_lp = out;                                   // (B,L,V)
    float* out_h  = out + (size_t)BB * LL * VV;            // (1,B,H)
    float* out_at = out_h + (size_t)BB * HH;               // (B,L,S)

    void* p;
    cudaGetSymbolAddress(&p, g_h);       float* p_h   = (float*)p;
    cudaGetSymbolAddress(&p, g_Uk);      float* p_Uk  = (float*)p;
    cudaGetSymbolAddress(&p, g_x);       float* p_x   = (float*)p;
    cudaGetSymbolAddress(&p, g_gi_part); float* p_gip = (float*)p;
    cudaGetSymbolAddress(&p, g_gh_part); float* p_ghp = (float*)p;
    cudaGetSymbolAddress(&p, g_logits);  float* p_lg  = (float*)p;

    // h0 = encoder_hidden[0] @ W_ht^T + b_ht          (M=32, N=512, K=512)
    gemm32<<<dim3(HH / 64, 1, 1), 128>>>(ehid, W_ht, b_ht, p_h, HH, EE, EE, 0);
    // Uk = enc @ Ua^T + bUa                           (M=8192, N=512, K=512)
    gemm32<<<dim3(HH / 64, (BB * SS) / 32, 1), 128>>>(enc, Ua, bUa, p_Uk, HH, EE, EE, 0);

    for (int t = 0; t < LL; t++) {
        att_step<<<BB, 512>>>(enc, tgt, emb, Wa, ba, Va, bVa, out_at, t);
        // gi partials: x(32,1024) @ W_ih^T -> 4-way split-K
        gemm32<<<dim3(G3 / 64, 1, 4), 128>>>(p_x, W_ih, nullptr, p_gip, G3, XD, XD / 4, BB * G3);
        // gh partials: h(32,512) @ W_hh^T -> 2-way split-K
        gemm32<<<dim3(G3 / 64, 1, 2), 128>>>(p_h, W_hh, nullptr, p_ghp, G3, HH, HH / 2, BB * G3);
        gru_gate<<<(BB * HH) / 256, 256>>>(b_ih, b_hh);
        // logits = h_new @ W_out^T + b_out            (M=32, N=32000, K=512)
        gemm32<<<dim3(VV / 64, 1, 1), 128>>>(p_h, W_out, b_out, p_lg, VV, HH, HH, 0);
        lsm_kernel<<<BB, 1024>>>(out_lp, t);
    }
    copy_h<<<(BB * HH) / 256, 256>>>(out_h);
}